// round 12
// baseline (speedup 1.0000x reference)
#include <cuda_runtime.h>
#include <math.h>

#define EPSF 1.1920929e-07f
typedef unsigned long long ull;

// ---------------- f32x2 packed-FMA helpers (sm_103a) ----------------
__device__ __forceinline__ ull f2pk(float a, float b) {
    ull r; asm("mov.b64 %0, {%1,%2};" : "=l"(r) : "f"(a), "f"(b)); return r;
}
__device__ __forceinline__ ull ffma2(ull a, ull b, ull c) {
    ull d; asm("fma.rn.f32x2 %0, %1, %2, %3;" : "=l"(d) : "l"(a), "l"(b), "l"(c)); return d;
}
__device__ __forceinline__ float2 f2up(ull v) {
    float2 f; asm("mov.b64 {%0,%1}, %2;" : "=f"(f.x), "=f"(f.y) : "l"(v)); return f;
}

// ---------------- scratch (__device__ globals; no allocations) ----------------
__device__ float d_logits[4096];                 // (8,512)
__device__ int   d_topk[32];                     // (8,4) sorted ascending
__device__ float d_Qb[8 * 8 * 65 * 128];         // (bh, s, c) rope+rms+tao q
__device__ float d_Kb[8 * 8 * 65 * 128];         // (bh, s, c)
__device__ float d_Vb[8 * 8 * 65 * 128];         // (bh, s, c)
__device__ float d_g[8 * 64 * 1024];             // gate logits (b, r, h, c)

// ---------------- K1: per-patch score logit; one warp per patch ----------------
__global__ __launch_bounds__(256) void k_score(const float* __restrict__ x,
                                               const float* __restrict__ pw) {
    int wid = threadIdx.x >> 5, lane = threadIdx.x & 31;
    int pid = blockIdx.x * 8 + wid;              // 512 blocks * 8 warps = 4096 patches
    const float4* xv = (const float4*)(x + (size_t)pid * 2048);
    const float4* pv = (const float4*)pw;
    float ss = 0.f, dp = 0.f;
#pragma unroll
    for (int i = 0; i < 16; i++) {
        float4 v = xv[i * 32 + lane];
        float4 w = pv[i * 32 + lane];
        ss += v.x * v.x + v.y * v.y + v.z * v.z + v.w * v.w;
        dp += v.x * w.x + v.y * w.y + v.z * w.z + v.w * w.w;
    }
#pragma unroll
    for (int o = 16; o; o >>= 1) {
        ss += __shfl_xor_sync(0xffffffffu, ss, o);
        dp += __shfl_xor_sync(0xffffffffu, dp, o);
    }
    if (lane == 0) d_logits[pid] = dp * rsqrtf(ss * (1.0f / 2048.0f) + EPSF);
}

// ---------------- K2: block0 = top-4 per batch; block1 = sink rows ----------------
__global__ __launch_bounds__(256) void k_topk_sink(const float* __restrict__ sink,
                                                   const float* __restrict__ tao) {
    int wid = threadIdx.x >> 5, lane = threadIdx.x & 31;
    if (blockIdx.x == 0) {
        int b = wid;
        float v[16];
#pragma unroll
        for (int i = 0; i < 16; i++) v[i] = d_logits[b * 512 + i * 32 + lane];
        int got[4];
#pragma unroll
        for (int r = 0; r < 4; r++) {
            float bv = -1e30f; int bi = 1 << 30;
#pragma unroll
            for (int i = 0; i < 16; i++) {
                int idx = i * 32 + lane;
                if (v[i] > bv || (v[i] == bv && idx < bi)) { bv = v[i]; bi = idx; }
            }
#pragma unroll
            for (int o = 16; o; o >>= 1) {
                float ov = __shfl_xor_sync(0xffffffffu, bv, o);
                int   oi = __shfl_xor_sync(0xffffffffu, bi, o);
                if (ov > bv || (ov == bv && oi < bi)) { bv = ov; bi = oi; }
            }
            got[r] = bi;
            if ((bi & 31) == lane) v[bi >> 5] = -1e30f;
        }
        if (lane == 0) {
#pragma unroll
            for (int i = 0; i < 4; i++)
#pragma unroll
                for (int j = 0; j < 3; j++)
                    if (got[j + 1] < got[j]) { int t = got[j]; got[j] = got[j + 1]; got[j + 1] = t; }
#pragma unroll
            for (int i = 0; i < 4; i++) d_topk[b * 4 + i] = got[i];
        }
    } else {
        // sink row s=0 per head (rope at s=0 is identity): Q/K = rmsnorm(sink)*tao, V = sink
        int h = wid;
        int c0 = lane * 4;
        float4 v = *(const float4*)(sink + h * 128 + c0);
        float ss = v.x * v.x + v.y * v.y + v.z * v.z + v.w * v.w;
#pragma unroll
        for (int o = 16; o; o >>= 1) ss += __shfl_xor_sync(0xffffffffu, ss, o);
        float n = rsqrtf(ss * (1.f / 128.f) + EPSF);
        float nq = n * tao[0], nk = n * tao[1];
        float4 q = make_float4(v.x * nq, v.y * nq, v.z * nq, v.w * nq);
        float4 k = make_float4(v.x * nk, v.y * nk, v.z * nk, v.w * nk);
#pragma unroll
        for (int b = 0; b < 8; b++) {
            size_t off = ((size_t)((b * 8 + h) * 65)) * 128 + c0;
            *(float4*)(d_Qb + off) = q;
            *(float4*)(d_Kb + off) = k;
            *(float4*)(d_Vb + off) = v;
        }
    }
}

// ---------------- K3: qkvg GEMM fused with rope+rmsnorm+tao epilogue ----------------
// grid (32 n-tiles, 8 batches), 256 threads; tile M=64 x N=128, K chunks of 32.
// Double-buffered: prefetch next kc chunk into registers during compute.
__global__ __launch_bounds__(256) void k_qkvg(const float* __restrict__ x,
                                              const float* __restrict__ W,
                                              const float* __restrict__ cosb,
                                              const float* __restrict__ sinb,
                                              const float* __restrict__ tao) {
    int nt = blockIdx.x, b = blockIdx.y;
    int tid = threadIdx.x;
    __shared__ __align__(16) float Xs[32][68];    // [k][m]
    __shared__ __align__(16) float Ws[32][132];   // [k][n]
    __shared__ int toks[64];
    if (tid < 64) toks[tid] = d_topk[b * 4 + (tid >> 4)] * 16 + (tid & 15);
    __syncthreads();
    int tx = tid & 15, ty = tid >> 4;
    int m0 = ty * 4, n0 = tx * 8;

    // per-thread load indices (fixed across kc)
    int mA = tid >> 3,            kqA = tid & 7;           // X jj=0
    int mB = (tid + 256) >> 3,    kqB = (tid + 256) & 7;   // X jj=1
    const float* xA = x + ((size_t)(b * 8192 + toks[mA])) * 128 + kqA * 4;
    const float* xB = x + ((size_t)(b * 8192 + toks[mB])) * 128 + kqB * 4;
    const float* wP[4];
    int cW[4], kqW[4];
#pragma unroll
    for (int jj = 0; jj < 4; jj++) {
        int idx = tid + jj * 256;
        cW[jj] = idx >> 3; kqW[jj] = idx & 7;
        wP[jj] = W + ((size_t)(nt * 128 + cW[jj])) * 128 + kqW[jj] * 4;
    }

    float4 xr0, xr1, wr[4];
    // prefetch kc=0
    xr0 = *(const float4*)(xA);
    xr1 = *(const float4*)(xB);
#pragma unroll
    for (int jj = 0; jj < 4; jj++) wr[jj] = *(const float4*)(wP[jj]);

    ull acc[4][4];
#pragma unroll
    for (int i = 0; i < 4; i++)
#pragma unroll
        for (int j = 0; j < 4; j++) acc[i][j] = 0ull;

#pragma unroll 1
    for (int kc = 0; kc < 4; kc++) {
        // store current regs to smem
        Xs[kqA * 4 + 0][mA] = xr0.x; Xs[kqA * 4 + 1][mA] = xr0.y;
        Xs[kqA * 4 + 2][mA] = xr0.z; Xs[kqA * 4 + 3][mA] = xr0.w;
        Xs[kqB * 4 + 0][mB] = xr1.x; Xs[kqB * 4 + 1][mB] = xr1.y;
        Xs[kqB * 4 + 2][mB] = xr1.z; Xs[kqB * 4 + 3][mB] = xr1.w;
#pragma unroll
        for (int jj = 0; jj < 4; jj++) {
            Ws[kqW[jj] * 4 + 0][cW[jj]] = wr[jj].x; Ws[kqW[jj] * 4 + 1][cW[jj]] = wr[jj].y;
            Ws[kqW[jj] * 4 + 2][cW[jj]] = wr[jj].z; Ws[kqW[jj] * 4 + 3][cW[jj]] = wr[jj].w;
        }
        __syncthreads();
        // prefetch next chunk while computing this one
        if (kc < 3) {
            int off = (kc + 1) * 32;
            xr0 = *(const float4*)(xA + off);
            xr1 = *(const float4*)(xB + off);
#pragma unroll
            for (int jj = 0; jj < 4; jj++) wr[jj] = *(const float4*)(wP[jj] + off);
        }
#pragma unroll
        for (int k = 0; k < 32; k++) {
            float4 xv = *(const float4*)&Xs[k][m0];
            ull xb0 = f2pk(xv.x, xv.x), xb1 = f2pk(xv.y, xv.y);
            ull xb2 = f2pk(xv.z, xv.z), xb3 = f2pk(xv.w, xv.w);
            const ull* wp = (const ull*)&Ws[k][n0];
            ull w0 = wp[0], w1 = wp[1], w2 = wp[2], w3 = wp[3];
            acc[0][0] = ffma2(xb0, w0, acc[0][0]); acc[0][1] = ffma2(xb0, w1, acc[0][1]);
            acc[0][2] = ffma2(xb0, w2, acc[0][2]); acc[0][3] = ffma2(xb0, w3, acc[0][3]);
            acc[1][0] = ffma2(xb1, w0, acc[1][0]); acc[1][1] = ffma2(xb1, w1, acc[1][1]);
            acc[1][2] = ffma2(xb1, w2, acc[1][2]); acc[1][3] = ffma2(xb1, w3, acc[1][3]);
            acc[2][0] = ffma2(xb2, w0, acc[2][0]); acc[2][1] = ffma2(xb2, w1, acc[2][1]);
            acc[2][2] = ffma2(xb2, w2, acc[2][2]); acc[2][3] = ffma2(xb2, w3, acc[2][3]);
            acc[3][0] = ffma2(xb3, w0, acc[3][0]); acc[3][1] = ffma2(xb3, w1, acc[3][1]);
            acc[3][2] = ffma2(xb3, w2, acc[3][2]); acc[3][3] = ffma2(xb3, w3, acc[3][3]);
        }
        __syncthreads();
    }

    // ---- fused epilogue ----
    int cb = nt >> 3, h = nt & 7;
    int cat = ty & 3;                             // 0=q 1=k 2=v 3=g (half-warp-uniform)
    int p = ty >> 2;
    int bh = b * 8 + h;
#pragma unroll
    for (int i = 0; i < 4; i++) {
        float r[8];
#pragma unroll
        for (int j = 0; j < 4; j++) {
            float2 f = f2up(acc[i][j]);
            r[2 * j] = f.x; r[2 * j + 1] = f.y;
        }
        int s0 = p * 16 + i * 4 + cb;             // row index within (b,h), 0..63
        int s = s0 + 1;
        if (cat < 2) {                            // q or k: rope + rmsnorm + tao
            float other[8];
#pragma unroll
            for (int c = 0; c < 8; c++) other[c] = __shfl_xor_sync(0xffffffffu, r[c], 8);
            int d0 = n0 & 63;
            float4 ca = *(const float4*)(cosb + s * 64 + d0);
            float4 cbv = *(const float4*)(cosb + s * 64 + d0 + 4);
            float4 sa = *(const float4*)(sinb + s * 64 + d0);
            float4 sb = *(const float4*)(sinb + s * 64 + d0 + 4);
            float cs[8] = {ca.x, ca.y, ca.z, ca.w, cbv.x, cbv.y, cbv.z, cbv.w};
            float sn[8] = {sa.x, sa.y, sa.z, sa.w, sb.x, sb.y, sb.z, sb.w};
            float sgn = (tx < 8) ? 1.f : -1.f;
            float rv[8], ssq = 0.f;
#pragma unroll
            for (int c = 0; c < 8; c++) {
                rv[c] = fmaf(r[c], cs[c], sgn * other[c] * sn[c]);
                ssq += rv[c] * rv[c];
            }
#pragma unroll
            for (int o = 8; o; o >>= 1) ssq += __shfl_xor_sync(0xffffffffu, ssq, o);
            float nrm = rsqrtf(ssq * (1.f / 128.f) + EPSF) * tao[cat];
            float* dst = (cat == 0 ? d_Qb : d_Kb) + ((size_t)bh * 65 + s) * 128 + n0;
            *(float4*)dst = make_float4(rv[0] * nrm, rv[1] * nrm, rv[2] * nrm, rv[3] * nrm);
            *(float4*)(dst + 4) = make_float4(rv[4] * nrm, rv[5] * nrm, rv[6] * nrm, rv[7] * nrm);
        } else if (cat == 2) {                    // v: raw
            float* dst = d_Vb + ((size_t)bh * 65 + s) * 128 + n0;
            *(float4*)dst = make_float4(r[0], r[1], r[2], r[3]);
            *(float4*)(dst + 4) = make_float4(r[4], r[5], r[6], r[7]);
        } else {                                  // g: raw gate logits
            float* dst = d_g + ((size_t)(b * 64 + s0)) * 1024 + h * 128 + n0;
            *(float4*)dst = make_float4(r[0], r[1], r[2], r[3]);
            *(float4*)(dst + 4) = make_float4(r[4], r[5], r[6], r[7]);
        }
    }
}

// ---------------- K5: causal attention + gate + OUTPUT PROJECTION, fused ----------------
// grid (4, 64), 256 threads. Chunk handles query rows s = rbase+1..rbase+16.
// After PV+gate, block multiplies its 16x128 y tile by Wout_h^T (128x128 slice)
// and atomicAdds the 16x128 result into out. Removes k_out and d_yg entirely.
__global__ __launch_bounds__(256) void k_attn_out(const float* __restrict__ Wout,
                                                  float* __restrict__ out) {
    __shared__ __align__(16) float Qc[32][18];    // [k][local row]
    __shared__ __align__(16) float Kc[32 * 68];   // [k][t]
    __shared__ __align__(16) float Ps[16 * 68];   // scores/probs
    __shared__ __align__(16) float ysm[16][132];  // gated attention rows
    __shared__ __align__(16) float Wsm[32][132];  // Wout_h chunk, [c][c_out]
    int chunk = blockIdx.x, bh = blockIdx.y;
    int b = bh >> 3, h = bh & 7;
    int tid = threadIdx.x;
    int wid = tid >> 5, lane = tid & 31;
    int rbase = chunk * 16;
    int text = rbase + 17;                        // 17 / 33 / 49 / 65
    const float* Qg = d_Qb + (size_t)bh * 65 * 128;
    const float* Kg = d_Kb + (size_t)bh * 65 * 128;
    const float* Vg = d_Vb + (size_t)bh * 65 * 128;
    int r0 = wid * 2;                             // local rows r0, r0+1
    int t0 = lane * 2;
    ull acc0 = 0ull, acc1 = 0ull;
    float e64 = 0.f;

#pragma unroll 1
    for (int kc = 0; kc < 4; kc++) {
        if (tid < 128) {                          // Q: 16 rows x 8 float4
            int r = tid >> 3, kq = tid & 7;
            float4 qv = *(const float4*)(Qg + (size_t)(rbase + r + 1) * 128 + kc * 32 + kq * 4);
            Qc[kq * 4 + 0][r] = qv.x; Qc[kq * 4 + 1][r] = qv.y;
            Qc[kq * 4 + 2][r] = qv.z; Qc[kq * 4 + 3][r] = qv.w;
        }
        for (int idx = tid; idx < text * 8; idx += 256) {
            int t = idx >> 3, kq = idx & 7;
            float4 kv = *(const float4*)(Kg + (size_t)t * 128 + kc * 32 + kq * 4);
            Kc[(kq * 4 + 0) * 68 + t] = kv.x; Kc[(kq * 4 + 1) * 68 + t] = kv.y;
            Kc[(kq * 4 + 2) * 68 + t] = kv.z; Kc[(kq * 4 + 3) * 68 + t] = kv.w;
        }
        __syncthreads();
#pragma unroll
        for (int k = 0; k < 32; k++) {
            ull qp = *(const ull*)&Qc[k][r0];      // rows r0, r0+1 (broadcast)
            float2 kv = *(const float2*)&Kc[k * 68 + t0];
            acc0 = ffma2(qp, f2pk(kv.x, kv.x), acc0);
            acc1 = ffma2(qp, f2pk(kv.y, kv.y), acc1);
        }
        if (chunk == 3 && tid == 0) {              // lone (s=64, t=64) element
#pragma unroll
            for (int k = 0; k < 32; k++) e64 += Qc[k][15] * Kc[k * 68 + 64];
        }
        __syncthreads();
    }
    {   // store raw scores
        float2 f0 = f2up(acc0), f1 = f2up(acc1);
        Ps[r0 * 68 + t0]           = f0.x;
        Ps[(r0 + 1) * 68 + t0]     = f0.y;
        Ps[r0 * 68 + t0 + 1]       = f1.x;
        Ps[(r0 + 1) * 68 + t0 + 1] = f1.y;
        if (chunk == 3 && tid == 0) Ps[15 * 68 + 64] = e64;
    }
    __syncthreads();

    // warp-parallel softmax: warp wid owns local rows r0, r0+1
    const float scl = 0.08838834764831845f;       // 1/sqrt(128)
#pragma unroll
    for (int rr = 0; rr < 2; rr++) {
        int lr = r0 + rr;
        int s = rbase + lr + 1;
        bool ok0 = (lane <= s);
        bool ok1 = (lane + 32 <= s);
        float v0 = ok0 ? Ps[lr * 68 + lane] * scl : -1e30f;
        float v1 = ok1 ? Ps[lr * 68 + lane + 32] * scl : -1e30f;
        float ve = (s == 64) ? Ps[lr * 68 + 64] * scl : -1e30f;   // warp-uniform
        float m = fmaxf(v0, v1);
#pragma unroll
        for (int o = 16; o; o >>= 1) m = fmaxf(m, __shfl_xor_sync(0xffffffffu, m, o));
        m = fmaxf(m, ve);
        float e0 = ok0 ? __expf(v0 - m) : 0.f;
        float e1 = ok1 ? __expf(v1 - m) : 0.f;
        float ee = (s == 64) ? __expf(ve - m) : 0.f;
        float sum = e0 + e1;
#pragma unroll
        for (int o = 16; o; o >>= 1) sum += __shfl_xor_sync(0xffffffffu, sum, o);
        sum += ee;
        float inv = 1.f / sum;
        Ps[lr * 68 + lane]      = e0 * inv;
        Ps[lr * 68 + lane + 32] = e1 * inv;
        if (lane == 0) Ps[lr * 68 + 64] = ee * inv;
    }
    __syncwarp();                                  // own-row Ps consistent within warp

    // PV: warp's 2 rows; lane owns channels c0..c0+3; V from global (L1/L2-shared)
    int c0 = lane * 4;
    ull y00 = 0ull, y01 = 0ull, y10 = 0ull, y11 = 0ull;
    const float* P0 = &Ps[r0 * 68];
    const float* P1 = &Ps[(r0 + 1) * 68];
#pragma unroll 4
    for (int t = 0; t < text; t++) {
        const ull* vp = (const ull*)(Vg + (size_t)t * 128 + c0);
        ull v0 = vp[0], v1 = vp[1];
        float p0 = P0[t], p1 = P1[t];
        ull pb0 = f2pk(p0, p0), pb1 = f2pk(p1, p1);
        y00 = ffma2(pb0, v0, y00); y01 = ffma2(pb0, v1, y01);
        y10 = ffma2(pb1, v0, y10); y11 = ffma2(pb1, v1, y11);
    }

    // gate with sigmoid(g), stage gated y into smem
#pragma unroll
    for (int rr = 0; rr < 2; rr++) {
        int r = rbase + r0 + rr;
        float4 g4 = *(const float4*)(d_g + ((size_t)(b * 64 + r)) * 1024 + h * 128 + c0);
        float2 ya = f2up(rr ? y10 : y00), yb = f2up(rr ? y11 : y01);
        float4 o;
        o.x = ya.x / (1.f + __expf(-g4.x));
        o.y = ya.y / (1.f + __expf(-g4.y));
        o.z = yb.x / (1.f + __expf(-g4.z));
        o.w = yb.y / (1.f + __expf(-g4.w));
        *(float4*)&ysm[r0 + rr][c0] = o;
    }
    __syncthreads();

    // ---- fused output projection: out_rows += ysm(16x128) @ Wout_h^T ----
    // thread (ty=row 0..15, tx=c_out block 0..15 of 8)
    int ty = tid >> 4, tx = tid & 15;
    ull pacc[4] = {0ull, 0ull, 0ull, 0ull};
#pragma unroll 1
    for (int cc4 = 0; cc4 < 4; cc4++) {
        // stage Wout[c_out][h*128 + cc4*32 + c] transposed -> Wsm[c][c_out]
#pragma unroll
        for (int jj = 0; jj < 4; jj++) {
            int idx = tid + jj * 256;              // 1024 float4 loads
            int co = idx >> 3, q = idx & 7;
            float4 w = *(const float4*)(Wout + (size_t)co * 1024 + h * 128 + cc4 * 32 + q * 4);
            Wsm[q * 4 + 0][co] = w.x; Wsm[q * 4 + 1][co] = w.y;
            Wsm[q * 4 + 2][co] = w.z; Wsm[q * 4 + 3][co] = w.w;
        }
        __syncthreads();
#pragma unroll
        for (int c = 0; c < 32; c++) {
            float yv = ysm[ty][cc4 * 32 + c];      // broadcast within half-warp
            ull pb = f2pk(yv, yv);
            const ull* wp = (const ull*)&Wsm[c][tx * 8];
            pacc[0] = ffma2(pb, wp[0], pacc[0]);
            pacc[1] = ffma2(pb, wp[1], pacc[1]);
            pacc[2] = ffma2(pb, wp[2], pacc[2]);
            pacc[3] = ffma2(pb, wp[3], pacc[3]);
        }
        __syncthreads();
    }
    float* dst = out + (size_t)(b * 64 + rbase + ty) * 128 + tx * 8;
#pragma unroll
    for (int j = 0; j < 4; j++) {
        float2 f = f2up(pacc[j]);
        atomicAdd(dst + 2 * j,     f.x);
        atomicAdd(dst + 2 * j + 1, f.y);
    }
}

// ---------------- launch ----------------
extern "C" void kernel_launch(void* const* d_in, const int* in_sizes, int n_in,
                              void* d_out, int out_size) {
    const float* x     = (const float*)d_in[0];
    const float* cosb  = (const float*)d_in[1];
    const float* sinb  = (const float*)d_in[2];
    const float* sink  = (const float*)d_in[3];
    const float* Wqkvg = (const float*)d_in[4];
    const float* pw    = (const float*)d_in[5];
    const float* Wout  = (const float*)d_in[6];
    const float* tao   = (const float*)d_in[7];
    float* out = (float*)d_out;

    cudaMemsetAsync(out, 0, (size_t)out_size * sizeof(float));
    k_score<<<512, 256>>>(x, pw);
    k_topk_sink<<<2, 256>>>(sink, tao);
    k_qkvg<<<dim3(32, 8), 256>>>(x, Wqkvg, cosb, sinb, tao);
    k_attn_out<<<dim3(4, 64), 256>>>(Wout, out);
}